// round 3
// baseline (speedup 1.0000x reference)
#include <cuda_runtime.h>

// Problem constants: x (B,I,C,T) fp32, weight (I*D,1,C,1) fp32
// out[b, i*D+d, 0, t] = sum_c x[b,i,c,t] * renorm(w)[i*D+d, c]
#define B_ 32
#define I_ 16
#define C_ 128
#define T_ 2048
#define D_ 8

__device__ __forceinline__ unsigned long long pack2(float lo, float hi) {
    unsigned long long r;
    asm("mov.b64 %0, {%1, %2};" : "=l"(r) : "f"(lo), "f"(hi));
    return r;
}

__device__ __forceinline__ void unpack2(unsigned long long v, float& lo, float& hi) {
    asm("mov.b64 {%0, %1}, %2;" : "=f"(lo), "=f"(hi) : "l"(v));
}

// Packed dual-fp32 FMA: d.lo = a.lo*b.lo + c.lo ; d.hi = a.hi*b.hi + c.hi
// (Blackwell FFMA2 — only reachable via PTX fma.rn.f32x2.)
__device__ __forceinline__ unsigned long long fma2(unsigned long long a,
                                                   unsigned long long b,
                                                   unsigned long long c) {
    unsigned long long d;
    asm("fma.rn.f32x2 %0, %1, %2, %3;" : "=l"(d) : "l"(a), "l"(b), "l"(c));
    return d;
}

__global__ __launch_bounds__(256) void dwconv_kernel(
    const float* __restrict__ x,
    const float* __restrict__ w,
    float* __restrict__ out)
{
    __shared__ float ws[D_ * C_];                 // raw weights for this i
    __shared__ unsigned long long ws2[D_ * C_];   // renormed, duplicated (w,w)
    __shared__ float scale_s[D_];

    const int tid = threadIdx.x;
    const int bid = blockIdx.x;
    // grid = B*I*2 : 2 t-chunks of 1024 per (b,i)
    const int tchunk = bid & 1;
    const int i      = (bid >> 1) & (I_ - 1);
    const int b      = bid >> 5;

    // Load this i's D_ weight rows (D_*C_ = 1024 floats)
    for (int idx = tid; idx < D_ * C_; idx += 256)
        ws[idx] = w[i * (D_ * C_) + idx];
    __syncthreads();

    // max-norm renorm: row (i*D+d) has C_ elements; scale = min(1, 1/norm)
    const int wid = tid >> 5, lane = tid & 31;
    if (wid < D_) {
        float s = 0.f;
        #pragma unroll
        for (int c = lane; c < C_; c += 32) {
            float v = ws[wid * C_ + c];
            s += v * v;
        }
        #pragma unroll
        for (int off = 16; off > 0; off >>= 1)
            s += __shfl_xor_sync(0xffffffffu, s, off);
        if (lane == 0) {
            float n = sqrtf(s);
            scale_s[wid] = (n > 1.0f) ? (1.0f / n) : 1.0f;
        }
    }
    __syncthreads();

    for (int idx = tid; idx < D_ * C_; idx += 256) {
        float v = ws[idx] * scale_s[idx >> 7];   // idx/128 = d
        ws2[idx] = pack2(v, v);
    }
    __syncthreads();

    // Each thread: 4 consecutive t via float4; block covers 1024 t.
    const int t0 = tchunk * 1024 + tid * 4;
    const float4* __restrict__ xp = reinterpret_cast<const float4*>(
        x + (size_t)(b * I_ + i) * C_ * T_ + t0);
    const int xstride4 = T_ / 4;  // float4 stride between c rows

    unsigned long long acc01[D_], acc23[D_];
    #pragma unroll
    for (int d = 0; d < D_; d++) { acc01[d] = 0ull; acc23[d] = 0ull; }

    #pragma unroll 4
    for (int c = 0; c < C_; c++) {
        float4 xv = __ldg(&xp[(size_t)c * xstride4]);
        unsigned long long x01 = pack2(xv.x, xv.y);
        unsigned long long x23 = pack2(xv.z, xv.w);
        #pragma unroll
        for (int d = 0; d < D_; d++) {
            unsigned long long wv = ws2[d * C_ + c];   // broadcast LDS.64
            acc01[d] = fma2(x01, wv, acc01[d]);
            acc23[d] = fma2(x23, wv, acc23[d]);
        }
    }

    float4* __restrict__ op = reinterpret_cast<float4*>(
        out + (size_t)(b * (I_ * D_) + i * D_) * T_ + t0);
    #pragma unroll
    for (int d = 0; d < D_; d++) {
        float4 o;
        unpack2(acc01[d], o.x, o.y);
        unpack2(acc23[d], o.z, o.w);
        op[(size_t)d * (T_ / 4)] = o;
    }
}

extern "C" void kernel_launch(void* const* d_in, const int* in_sizes, int n_in,
                              void* d_out, int out_size) {
    const float* x = (const float*)d_in[0];   // (32,16,128,2048) fp32
    const float* w = (const float*)d_in[1];   // (256,1,128,1)    fp32
    float* out = (float*)d_out;               // (32,256,1,2048)  fp32

    (void)in_sizes; (void)n_in; (void)out_size;

    const int grid = B_ * I_ * (T_ / 1024);   // 1024 blocks
    dwconv_kernel<<<grid, 256>>>(x, w, out);
}

// round 4
// speedup vs baseline: 1.8482x; 1.8482x over previous
#include <cuda_runtime.h>
#include <cstdint>

// out[b, i*D+d, 0, t] = sum_c x[b,i,c,t] * renorm(w)[i*D+d, c]
#define B_ 32
#define I_ 16
#define C_ 128
#define T_ 2048
#define D_ 8
#define DEPTH 8   // cp.async pipeline depth (power of 2)

// Pre-renormed weights, duplicated as (w,w) u64 pairs for fma.f32x2. 16 KB.
__device__ unsigned long long g_ws2[I_ * D_ * C_];

__device__ __forceinline__ unsigned long long pack2(float lo, float hi) {
    unsigned long long r;
    asm("mov.b64 %0, {%1, %2};" : "=l"(r) : "f"(lo), "f"(hi));
    return r;
}
__device__ __forceinline__ void unpack2(unsigned long long v, float& lo, float& hi) {
    asm("mov.b64 {%0, %1}, %2;" : "=f"(lo), "=f"(hi) : "l"(v));
}
// Packed dual-fp32 FMA (Blackwell FFMA2, PTX-only).
__device__ __forceinline__ unsigned long long fma2(unsigned long long a,
                                                   unsigned long long b,
                                                   unsigned long long c) {
    unsigned long long d;
    asm("fma.rn.f32x2 %0, %1, %2, %3;" : "=l"(d) : "l"(a), "l"(b), "l"(c));
    return d;
}

__device__ __forceinline__ void cp_async16(uint32_t saddr, const float* gaddr) {
    asm volatile("cp.async.cg.shared.global [%0], [%1], 16;"
                 :: "r"(saddr), "l"(gaddr));
}
__device__ __forceinline__ void cp_commit() {
    asm volatile("cp.async.commit_group;" ::: "memory");
}
template <int N>
__device__ __forceinline__ void cp_wait() {
    asm volatile("cp.async.wait_group %0;" :: "n"(N) : "memory");
}

// ---------------------------------------------------------------------------
// Prep kernel: max-norm renorm of weight rows, write duplicated u64 weights.
// One warp per out-channel row (128 rows). <<<16, 256>>>
// ---------------------------------------------------------------------------
__global__ void prep_kernel(const float* __restrict__ w) {
    const int wid = threadIdx.x >> 5, lane = threadIdx.x & 31;
    const int row = blockIdx.x * 8 + wid;            // 0..127 = i*D+d
    const float* wr = w + row * C_;

    float v0 = wr[lane], v1 = wr[lane + 32], v2 = wr[lane + 64], v3 = wr[lane + 96];
    float s = v0 * v0 + v1 * v1 + v2 * v2 + v3 * v3;
    #pragma unroll
    for (int off = 16; off > 0; off >>= 1)
        s += __shfl_xor_sync(0xffffffffu, s, off);
    float n = sqrtf(s);
    float scale = (n > 1.0f) ? (1.0f / n) : 1.0f;

    unsigned long long* dst = g_ws2 + row * C_;
    dst[lane]      = pack2(v0 * scale, v0 * scale);
    dst[lane + 32] = pack2(v1 * scale, v1 * scale);
    dst[lane + 64] = pack2(v2 * scale, v2 * scale);
    dst[lane + 96] = pack2(v3 * scale, v3 * scale);
}

// ---------------------------------------------------------------------------
// Main kernel: block = one (b, i, t-chunk of 1024). Thread owns 4 consecutive t.
// x streamed through an 8-deep thread-private cp.async smem ring.
// ---------------------------------------------------------------------------
__global__ __launch_bounds__(256, 4) void dwconv_kernel(
    const float* __restrict__ x,
    float* __restrict__ out)
{
    __shared__ __align__(16) float4 xs[DEPTH][256];        // 32 KB ring
    __shared__ __align__(16) unsigned long long ws2[D_ * C_];  // 8 KB weights

    const int tid = threadIdx.x;
    const int bid = blockIdx.x;
    const int tchunk = bid & 1;
    const int i      = (bid >> 1) & (I_ - 1);
    const int b      = bid >> 5;

    const int t0 = tchunk * 1024 + tid * 4;
    const float* xg = x + (size_t)(b * I_ + i) * C_ * T_ + t0;

    const uint32_t xs_base =
        (uint32_t)__cvta_generic_to_shared(&xs[0][0]) + (uint32_t)tid * 16u;

    // Kick off the pipeline before anything else touches memory.
    #pragma unroll
    for (int s = 0; s < DEPTH; s++) {
        cp_async16(xs_base + (uint32_t)s * (256u * 16u), xg + (size_t)s * T_);
        cp_commit();
    }

    // Copy this i's renormed weights (8 KB) into smem.
    {
        const float4* gw4 = reinterpret_cast<const float4*>(g_ws2 + i * (D_ * C_));
        float4* sw4 = reinterpret_cast<float4*>(ws2);
        sw4[tid]       = gw4[tid];
        sw4[tid + 256] = gw4[tid + 256];
    }
    __syncthreads();

    unsigned long long acc01[D_], acc23[D_];
    #pragma unroll
    for (int d = 0; d < D_; d++) { acc01[d] = 0ull; acc23[d] = 0ull; }

    const float* xg_pf = xg + (size_t)DEPTH * T_;   // prefetch pointer base

    #pragma unroll 8
    for (int c = 0; c < C_; c++) {
        cp_wait<DEPTH - 1>();   // oldest group (stage c) landed

        float4 xv = xs[c & (DEPTH - 1)][tid];
        unsigned long long x01 = pack2(xv.x, xv.y);
        unsigned long long x23 = pack2(xv.z, xv.w);

        #pragma unroll
        for (int d = 0; d < D_; d++) {
            unsigned long long wv = ws2[d * C_ + c];   // broadcast LDS.64
            acc01[d] = fma2(x01, wv, acc01[d]);
            acc23[d] = fma2(x23, wv, acc23[d]);
        }

        // Refill the slot just consumed (thread-private: no barrier needed).
        if (c < C_ - DEPTH)
            cp_async16(xs_base + (uint32_t)(c & (DEPTH - 1)) * (256u * 16u),
                       xg_pf + (size_t)c * T_);
        cp_commit();   // commit every iter (possibly empty) to keep accounting
    }

    float4* __restrict__ op = reinterpret_cast<float4*>(
        out + (size_t)(b * (I_ * D_) + i * D_) * T_ + t0);
    #pragma unroll
    for (int d = 0; d < D_; d++) {
        float4 o;
        unpack2(acc01[d], o.x, o.y);
        unpack2(acc23[d], o.z, o.w);
        op[(size_t)d * (T_ / 4)] = o;
    }
}

extern "C" void kernel_launch(void* const* d_in, const int* in_sizes, int n_in,
                              void* d_out, int out_size) {
    const float* x = (const float*)d_in[0];   // (32,16,128,2048) fp32
    const float* w = (const float*)d_in[1];   // (256,1,128,1)    fp32
    float* out = (float*)d_out;               // (32,256,1,2048)  fp32
    (void)in_sizes; (void)n_in; (void)out_size;

    prep_kernel<<<16, 256>>>(w);
    dwconv_kernel<<<B_ * I_ * (T_ / 1024), 256>>>(x, out);
}